// round 3
// baseline (speedup 1.0000x reference)
#include <cuda_runtime.h>
#include <math.h>

#define N_NODES 16384
#define N_EDGES 262144
#define H 128
#define F 128
#define G 50
#define GP 52          // padded gaussians for float4
#define L 6
#define NGRAPH 16
#define TE 32          // edges per tile
#define TN 32          // nodes per tile

// ---------------- device scratch (no allocation allowed) ----------------
__device__ float g_ea[(size_t)N_EDGES * GP];   // 54.5 MB smeared distances (padded)
__device__ float g_C[N_EDGES];                 // cosine cutoff
__device__ float g_h[(size_t)N_NODES * H];     // node features
__device__ float g_xh[(size_t)N_NODES * F];    // h @ cf_w1
__device__ float g_agg[(size_t)N_NODES * F];   // scatter-add target

__device__ __forceinline__ float ssp(float x) {
    // shifted softplus, numerically stable
    return log1pf(__expf(-fabsf(x))) + fmaxf(x, 0.0f) - 0.69314718055994531f;
}

// ---------------- init: h = emb[z] ----------------
__global__ void k_init_h(const int* __restrict__ z, const float* __restrict__ emb) {
    int i = blockIdx.x * blockDim.x + threadIdx.x;
    if (i < N_NODES * H) {
        int n = i >> 7, j = i & 127;
        g_h[i] = emb[z[n] * H + j];
    }
}

// ---------------- geometry: ew, C, ea ----------------
__global__ void k_geom(const float* __restrict__ pos, const int* __restrict__ ei) {
    __shared__ float ew_sh[128];
    int e = blockIdx.x * 128 + threadIdx.x;
    const int* row = ei;
    const int* col = ei + N_EDGES;
    int r = row[e], c = col[e];
    float dx = pos[r * 3 + 0] - pos[c * 3 + 0];
    float dy = pos[r * 3 + 1] - pos[c * 3 + 1];
    float dz = pos[r * 3 + 2] - pos[c * 3 + 2];
    dx -= rintf(dx * 0.2f) * 5.0f;
    dy -= rintf(dy * 0.2f) * 5.0f;
    dz -= rintf(dz * 0.2f) * 5.0f;
    float ew = sqrtf(dx * dx + dy * dy + dz * dz);
    ew_sh[threadIdx.x] = ew;
    float Cv = (ew < 10.0f) ? 0.5f * (cosf(ew * 0.31415926535897932f) + 1.0f) : 0.0f;
    g_C[e] = Cv;
    __syncthreads();
    const float step = 10.0f / 49.0f;
    const float coeff = -0.5f / (step * step);
    size_t base = (size_t)blockIdx.x * 128 * GP;
    for (int i = threadIdx.x; i < 128 * GP; i += 128) {
        int le = i / GP, g = i % GP;
        float v = 0.0f;
        if (g < G) {
            float d = ew_sh[le] - (float)g * step;
            v = __expf(coeff * d * d);
        }
        g_ea[base + i] = v;
    }
}

// ---------------- xh = h @ cf_w1[l]; zero agg ----------------
#define SMEM_XH ((F * F + TN * H) * 4)
__global__ __launch_bounds__(128) void k_xh(const float* __restrict__ w) {
    extern __shared__ float sm[];
    float* ws = sm;             // F*F
    float* tile = ws + F * F;   // TN*H
    int j = threadIdx.x;
    for (int i = j; i < F * F; i += 128) ws[i] = w[i];
    __syncthreads();
    const int ntiles = N_NODES / TN;
    for (int t = blockIdx.x; t < ntiles; t += gridDim.x) {
        int n0 = t * TN;
        for (int i = j; i < TN * H; i += 128) tile[i] = g_h[(size_t)n0 * H + i];
        __syncthreads();
        float acc[TN];
        #pragma unroll
        for (int n = 0; n < TN; n++) acc[n] = 0.0f;
        #pragma unroll 1
        for (int k4 = 0; k4 < H / 4; k4++) {
            float wa = ws[(4 * k4 + 0) * F + j];
            float wb = ws[(4 * k4 + 1) * F + j];
            float wc = ws[(4 * k4 + 2) * F + j];
            float wd = ws[(4 * k4 + 3) * F + j];
            #pragma unroll
            for (int n = 0; n < TN; n++) {
                float4 a = *(const float4*)&tile[n * H + 4 * k4];
                acc[n] = fmaf(a.x, wa, fmaf(a.y, wb, fmaf(a.z, wc, fmaf(a.w, wd, acc[n]))));
            }
        }
        #pragma unroll
        for (int n = 0; n < TN; n++) {
            g_xh[(size_t)(n0 + n) * F + j] = acc[n];
            g_agg[(size_t)(n0 + n) * F + j] = 0.0f;
        }
        __syncthreads();
    }
}

// ---------------- fused edge kernel ----------------
#define SMEM_EDGE ((GP * F + F * F + 2 * F + TE * F) * 4)
__global__ __launch_bounds__(128) void k_edge(
    const float* __restrict__ w1, const float* __restrict__ b1,
    const float* __restrict__ w2, const float* __restrict__ b2,
    const int* __restrict__ ei)
{
    extern __shared__ float sm[];
    float* w1s = sm;                 // GP*F (padded, rows 50/51 zero)
    float* w2s = w1s + GP * F;       // F*F
    float* b1s = w2s + F * F;        // F
    float* b2s = b1s + F;            // F
    float* tile = b2s + F;           // TE*F floats (union: ea tile TE*GP | t tile TE*F)
    int j = threadIdx.x;
    for (int i = j; i < GP * F; i += 128) w1s[i] = (i < G * F) ? w1[i] : 0.0f;
    for (int i = j; i < F * F; i += 128) w2s[i] = w2[i];
    b1s[j] = b1[j];
    b2s[j] = b2[j];
    const int* row = ei;
    const int* col = ei + N_EDGES;
    __syncthreads();
    const int ntiles = N_EDGES / TE;
    for (int t = blockIdx.x; t < ntiles; t += gridDim.x) {
        int e0 = t * TE;
        for (int i = j; i < TE * GP; i += 128) tile[i] = g_ea[(size_t)e0 * GP + i];
        __syncthreads();
        float acc[TE];
        #pragma unroll
        for (int e = 0; e < TE; e++) acc[e] = b1s[j];
        // GEMM1: t = ea @ w1 + b1
        #pragma unroll 1
        for (int g4 = 0; g4 < GP / 4; g4++) {
            float wa = w1s[(4 * g4 + 0) * F + j];
            float wb = w1s[(4 * g4 + 1) * F + j];
            float wc = w1s[(4 * g4 + 2) * F + j];
            float wd = w1s[(4 * g4 + 3) * F + j];
            #pragma unroll
            for (int e = 0; e < TE; e++) {
                float4 a = *(const float4*)&tile[e * GP + 4 * g4];
                acc[e] = fmaf(a.x, wa, fmaf(a.y, wb, fmaf(a.z, wc, fmaf(a.w, wd, acc[e]))));
            }
        }
        __syncthreads();   // everyone done reading ea before overwrite
        #pragma unroll
        for (int e = 0; e < TE; e++) tile[e * F + j] = ssp(acc[e]);
        __syncthreads();
        // GEMM2: W = t @ w2 + b2
        #pragma unroll
        for (int e = 0; e < TE; e++) acc[e] = b2s[j];
        #pragma unroll 1
        for (int k4 = 0; k4 < F / 4; k4++) {
            float wa = w2s[(4 * k4 + 0) * F + j];
            float wb = w2s[(4 * k4 + 1) * F + j];
            float wc = w2s[(4 * k4 + 2) * F + j];
            float wd = w2s[(4 * k4 + 3) * F + j];
            #pragma unroll
            for (int e = 0; e < TE; e++) {
                float4 a = *(const float4*)&tile[e * F + 4 * k4];
                acc[e] = fmaf(a.x, wa, fmaf(a.y, wb, fmaf(a.z, wc, fmaf(a.w, wd, acc[e]))));
            }
        }
        // epilogue: gather xh[row], modulate, scatter-add to agg[col]
        #pragma unroll
        for (int e = 0; e < TE; e++) {
            int eg = e0 + e;
            float Wv = acc[e] * g_C[eg];
            float m = g_xh[(size_t)row[eg] * F + j] * Wv;
            atomicAdd(&g_agg[(size_t)col[eg] * F + j], m);
        }
        __syncthreads();
    }
}

// ---------------- node update: h += ssp(agg@cf_w2+b2) @ lin_w + lin_b ----------------
#define SMEM_UPD ((F * H + H * H + 2 * H + TN * H) * 4)
__global__ __launch_bounds__(128) void k_update(
    const float* __restrict__ w2, const float* __restrict__ b2,
    const float* __restrict__ lw, const float* __restrict__ lb)
{
    extern __shared__ float sm[];
    float* w2s = sm;                // F*H
    float* lws = w2s + F * H;       // H*H
    float* b2s = lws + H * H;       // H
    float* lbs = b2s + H;           // H
    float* tile = lbs + H;          // TN*H (union: agg tile | s tile)
    int j = threadIdx.x;
    for (int i = j; i < F * H; i += 128) w2s[i] = w2[i];
    for (int i = j; i < H * H; i += 128) lws[i] = lw[i];
    b2s[j] = b2[j];
    lbs[j] = lb[j];
    __syncthreads();
    const int ntiles = N_NODES / TN;
    for (int t = blockIdx.x; t < ntiles; t += gridDim.x) {
        int n0 = t * TN;
        for (int i = j; i < TN * H; i += 128) tile[i] = g_agg[(size_t)n0 * H + i];
        __syncthreads();
        float acc[TN];
        #pragma unroll
        for (int n = 0; n < TN; n++) acc[n] = b2s[j];
        #pragma unroll 1
        for (int k4 = 0; k4 < F / 4; k4++) {
            float wa = w2s[(4 * k4 + 0) * H + j];
            float wb = w2s[(4 * k4 + 1) * H + j];
            float wc = w2s[(4 * k4 + 2) * H + j];
            float wd = w2s[(4 * k4 + 3) * H + j];
            #pragma unroll
            for (int n = 0; n < TN; n++) {
                float4 a = *(const float4*)&tile[n * H + 4 * k4];
                acc[n] = fmaf(a.x, wa, fmaf(a.y, wb, fmaf(a.z, wc, fmaf(a.w, wd, acc[n]))));
            }
        }
        __syncthreads();
        #pragma unroll
        for (int n = 0; n < TN; n++) tile[n * H + j] = ssp(acc[n]);
        __syncthreads();
        #pragma unroll
        for (int n = 0; n < TN; n++) acc[n] = lbs[j];
        #pragma unroll 1
        for (int k4 = 0; k4 < H / 4; k4++) {
            float wa = lws[(4 * k4 + 0) * H + j];
            float wb = lws[(4 * k4 + 1) * H + j];
            float wc = lws[(4 * k4 + 2) * H + j];
            float wd = lws[(4 * k4 + 3) * H + j];
            #pragma unroll
            for (int n = 0; n < TN; n++) {
                float4 a = *(const float4*)&tile[n * H + 4 * k4];
                acc[n] = fmaf(a.x, wa, fmaf(a.y, wb, fmaf(a.z, wc, fmaf(a.w, wd, acc[n]))));
            }
        }
        #pragma unroll
        for (int n = 0; n < TN; n++) g_h[(size_t)(n0 + n) * H + j] += acc[n];
        __syncthreads();
    }
}

// ---------------- readout ----------------
#define H2 64
#define SMEM_RO ((H * H2 + H2 + H2 + TN * H + TN * 65) * 4)
__global__ __launch_bounds__(128) void k_readout(
    const float* __restrict__ w1, const float* __restrict__ b1,
    const float* __restrict__ w2, const float* __restrict__ b2,
    const int* __restrict__ batch, float* __restrict__ out)
{
    extern __shared__ float sm[];
    float* w1s = sm;                 // H*H2
    float* b1s = w1s + H * H2;       // H2
    float* w2s = b1s + H2;           // H2
    float* tile = w2s + H2;          // TN*H
    float* sbuf = tile + TN * H;     // TN*65 (padded)
    int j = threadIdx.x;
    for (int i = j; i < H * H2; i += 128) w1s[i] = w1[i];
    if (j < H2) { b1s[j] = b1[j]; w2s[j] = w2[j]; }
    float b2v = b2[0];
    __syncthreads();
    const int ntiles = N_NODES / TN;
    for (int t = blockIdx.x; t < ntiles; t += gridDim.x) {
        int n0 = t * TN;
        for (int i = j; i < TN * H; i += 128) tile[i] = g_h[(size_t)n0 * H + i];
        __syncthreads();
        if (j < H2) {
            float acc[TN];
            #pragma unroll
            for (int n = 0; n < TN; n++) acc[n] = b1s[j];
            #pragma unroll 1
            for (int k4 = 0; k4 < H / 4; k4++) {
                float wa = w1s[(4 * k4 + 0) * H2 + j];
                float wb = w1s[(4 * k4 + 1) * H2 + j];
                float wc = w1s[(4 * k4 + 2) * H2 + j];
                float wd = w1s[(4 * k4 + 3) * H2 + j];
                #pragma unroll
                for (int n = 0; n < TN; n++) {
                    float4 a = *(const float4*)&tile[n * H + 4 * k4];
                    acc[n] = fmaf(a.x, wa, fmaf(a.y, wb, fmaf(a.z, wc, fmaf(a.w, wd, acc[n]))));
                }
            }
            #pragma unroll
            for (int n = 0; n < TN; n++) sbuf[n * 65 + j] = ssp(acc[n]);
        }
        __syncthreads();
        if (j < TN) {
            int n = j;
            float v = b2v;
            #pragma unroll 1
            for (int q = 0; q < H2; q++) v += sbuf[n * 65 + q] * w2s[q];
            atomicAdd(&out[batch[n0 + n]], v);
        }
        __syncthreads();
    }
}

__global__ void k_zero_out(float* out) {
    if (threadIdx.x < NGRAPH) out[threadIdx.x] = 0.0f;
}
__global__ void k_sigmoid(float* out) {
    if (threadIdx.x < NGRAPH) {
        float v = out[threadIdx.x];
        out[threadIdx.x] = 1.0f / (1.0f + __expf(-v));
    }
}

// ---------------- host launcher ----------------
extern "C" void kernel_launch(void* const* d_in, const int* in_sizes, int n_in,
                              void* d_out, int out_size) {
    const int*   z      = (const int*)d_in[0];
    const float* pos    = (const float*)d_in[1];
    const int*   ei     = (const int*)d_in[2];
    const int*   batch  = (const int*)d_in[3];
    const float* emb    = (const float*)d_in[4];
    const float* mlp_w1 = (const float*)d_in[5];
    const float* mlp_b1 = (const float*)d_in[6];
    const float* mlp_w2 = (const float*)d_in[7];
    const float* mlp_b2 = (const float*)d_in[8];
    const float* cf_w1  = (const float*)d_in[9];
    const float* cf_w2  = (const float*)d_in[10];
    const float* cf_b2  = (const float*)d_in[11];
    const float* lin_w  = (const float*)d_in[12];
    const float* lin_b  = (const float*)d_in[13];
    const float* out_w1 = (const float*)d_in[14];
    const float* out_b1 = (const float*)d_in[15];
    const float* out_w2 = (const float*)d_in[16];
    const float* out_b2 = (const float*)d_in[17];
    float* out = (float*)d_out;

    cudaFuncSetAttribute((const void*)k_edge,    cudaFuncAttributeMaxDynamicSharedMemorySize, SMEM_EDGE);
    cudaFuncSetAttribute((const void*)k_xh,      cudaFuncAttributeMaxDynamicSharedMemorySize, SMEM_XH);
    cudaFuncSetAttribute((const void*)k_update,  cudaFuncAttributeMaxDynamicSharedMemorySize, SMEM_UPD);
    cudaFuncSetAttribute((const void*)k_readout, cudaFuncAttributeMaxDynamicSharedMemorySize, SMEM_RO);

    k_init_h<<<(N_NODES * H) / 256, 256>>>(z, emb);
    k_geom<<<N_EDGES / 128, 128>>>(pos, ei);

    for (int l = 0; l < L; l++) {
        k_xh<<<296, 128, SMEM_XH>>>(cf_w1 + (size_t)l * H * F);
        k_edge<<<296, 128, SMEM_EDGE>>>(mlp_w1 + (size_t)l * G * F,
                                        mlp_b1 + (size_t)l * F,
                                        mlp_w2 + (size_t)l * F * F,
                                        mlp_b2 + (size_t)l * F,
                                        ei);
        k_update<<<148, 128, SMEM_UPD>>>(cf_w2 + (size_t)l * F * H,
                                         cf_b2 + (size_t)l * H,
                                         lin_w + (size_t)l * H * H,
                                         lin_b + (size_t)l * H);
    }

    k_zero_out<<<1, 32>>>(out);
    k_readout<<<296, 128, SMEM_RO>>>(out_w1, out_b1, out_w2, out_b2, batch, out);
    k_sigmoid<<<1, 32>>>(out);
}

// round 4
// speedup vs baseline: 1.1977x; 1.1977x over previous
#include <cuda_runtime.h>
#include <math.h>

#define N_NODES 16384
#define N_EDGES 262144
#define H 128
#define F 128
#define G 50
#define GP 52          // padded gaussians for float4
#define L 6
#define NGRAPH 16
#define TE 32          // edges per tile
#define TN 32          // nodes per tile
#define NT 512         // threads per block (4 groups x 128 channels)
#define EPG 8          // edges per group (TE / 4)

// ---------------- device scratch (no allocation allowed) ----------------
__device__ float g_ea[(size_t)N_EDGES * GP];   // 54.5 MB smeared distances (padded)
__device__ float g_C[N_EDGES];                 // cosine cutoff
__device__ float g_h[(size_t)N_NODES * H];     // node features
__device__ float g_xh[(size_t)N_NODES * F];    // h @ cf_w1
__device__ float g_agg[(size_t)N_NODES * F];   // scatter-add target

__device__ __forceinline__ float ssp(float x) {
    return log1pf(__expf(-fabsf(x))) + fmaxf(x, 0.0f) - 0.69314718055994531f;
}

// ---------------- init: h = emb[z] ----------------
__global__ void k_init_h(const int* __restrict__ z, const float* __restrict__ emb) {
    int i = blockIdx.x * blockDim.x + threadIdx.x;
    if (i < N_NODES * H) {
        int n = i >> 7, j = i & 127;
        g_h[i] = emb[z[n] * H + j];
    }
}

// ---------------- geometry: ew, C, ea ----------------
__global__ void k_geom(const float* __restrict__ pos, const int* __restrict__ ei) {
    __shared__ float ew_sh[128];
    int e = blockIdx.x * 128 + threadIdx.x;
    const int* row = ei;
    const int* col = ei + N_EDGES;
    int r = row[e], c = col[e];
    float dx = pos[r * 3 + 0] - pos[c * 3 + 0];
    float dy = pos[r * 3 + 1] - pos[c * 3 + 1];
    float dz = pos[r * 3 + 2] - pos[c * 3 + 2];
    dx -= rintf(dx * 0.2f) * 5.0f;
    dy -= rintf(dy * 0.2f) * 5.0f;
    dz -= rintf(dz * 0.2f) * 5.0f;
    float ew = sqrtf(dx * dx + dy * dy + dz * dz);
    ew_sh[threadIdx.x] = ew;
    float Cv = (ew < 10.0f) ? 0.5f * (cosf(ew * 0.31415926535897932f) + 1.0f) : 0.0f;
    g_C[e] = Cv;
    __syncthreads();
    const float step = 10.0f / 49.0f;
    const float coeff = -0.5f / (step * step);
    size_t base = (size_t)blockIdx.x * 128 * GP;
    for (int i = threadIdx.x; i < 128 * GP; i += 128) {
        int le = i / GP, g = i % GP;
        float v = 0.0f;
        if (g < G) {
            float d = ew_sh[le] - (float)g * step;
            v = __expf(coeff * d * d);
        }
        g_ea[base + i] = v;
    }
}

// ---------------- xh = h @ cf_w1[l]; zero agg ----------------
#define SMEM_XH ((F * F + TN * H) * 4)
__global__ __launch_bounds__(NT, 2) void k_xh(const float* __restrict__ w) {
    extern __shared__ float sm[];
    float* ws = sm;             // F*F
    float* tile = ws + F * F;   // TN*H
    int tid = threadIdx.x;
    int j = tid & 127;
    int grp = tid >> 7;
    for (int i = tid; i < F * F; i += NT) ws[i] = w[i];
    __syncthreads();
    const int ntiles = N_NODES / TN;
    for (int t = blockIdx.x; t < ntiles; t += gridDim.x) {
        int n0 = t * TN;
        for (int i = tid; i < TN * H; i += NT) tile[i] = g_h[(size_t)n0 * H + i];
        __syncthreads();
        float acc[EPG];
        #pragma unroll
        for (int n = 0; n < EPG; n++) acc[n] = 0.0f;
        #pragma unroll 1
        for (int k4 = 0; k4 < H / 4; k4++) {
            float wa = ws[(4 * k4 + 0) * F + j];
            float wb = ws[(4 * k4 + 1) * F + j];
            float wc = ws[(4 * k4 + 2) * F + j];
            float wd = ws[(4 * k4 + 3) * F + j];
            #pragma unroll
            for (int n = 0; n < EPG; n++) {
                float4 a = *(const float4*)&tile[(grp * EPG + n) * H + 4 * k4];
                acc[n] = fmaf(a.x, wa, fmaf(a.y, wb, fmaf(a.z, wc, fmaf(a.w, wd, acc[n]))));
            }
        }
        #pragma unroll
        for (int n = 0; n < EPG; n++) {
            int ng = n0 + grp * EPG + n;
            g_xh[(size_t)ng * F + j] = acc[n];
            g_agg[(size_t)ng * F + j] = 0.0f;
        }
        __syncthreads();
    }
}

// ---------------- fused edge kernel ----------------
#define SMEM_EDGE ((GP * F + F * F + 2 * F + TE * F) * 4)
__global__ __launch_bounds__(NT, 2) void k_edge(
    const float* __restrict__ w1, const float* __restrict__ b1,
    const float* __restrict__ w2, const float* __restrict__ b2,
    const int* __restrict__ ei)
{
    extern __shared__ float sm[];
    float* w1s = sm;                 // GP*F (padded, rows 50/51 zero)
    float* w2s = w1s + GP * F;       // F*F
    float* b1s = w2s + F * F;        // F
    float* b2s = b1s + F;            // F
    float* tile = b2s + F;           // TE*F floats (union: ea tile TE*GP | t tile TE*F)
    int tid = threadIdx.x;
    int j = tid & 127;
    int grp = tid >> 7;              // 0..3, edge subgroup
    for (int i = tid; i < GP * F; i += NT) w1s[i] = (i < G * F) ? w1[i] : 0.0f;
    for (int i = tid; i < F * F; i += NT) w2s[i] = w2[i];
    if (tid < F) { b1s[tid] = b1[tid]; b2s[tid] = b2[tid]; }
    const int* row = ei;
    const int* col = ei + N_EDGES;
    __syncthreads();
    const int ntiles = N_EDGES / TE;
    for (int t = blockIdx.x; t < ntiles; t += gridDim.x) {
        int e0 = t * TE;
        for (int i = tid; i < TE * GP; i += NT) tile[i] = g_ea[(size_t)e0 * GP + i];
        __syncthreads();
        float acc[EPG];
        #pragma unroll
        for (int e = 0; e < EPG; e++) acc[e] = b1s[j];
        // GEMM1: t = ea @ w1 + b1
        #pragma unroll 1
        for (int g4 = 0; g4 < GP / 4; g4++) {
            float wa = w1s[(4 * g4 + 0) * F + j];
            float wb = w1s[(4 * g4 + 1) * F + j];
            float wc = w1s[(4 * g4 + 2) * F + j];
            float wd = w1s[(4 * g4 + 3) * F + j];
            #pragma unroll
            for (int e = 0; e < EPG; e++) {
                float4 a = *(const float4*)&tile[(grp * EPG + e) * GP + 4 * g4];
                acc[e] = fmaf(a.x, wa, fmaf(a.y, wb, fmaf(a.z, wc, fmaf(a.w, wd, acc[e]))));
            }
        }
        __syncthreads();   // everyone done reading ea before overwrite
        #pragma unroll
        for (int e = 0; e < EPG; e++) tile[(grp * EPG + e) * F + j] = ssp(acc[e]);
        __syncthreads();
        // GEMM2: W = t @ w2 + b2
        #pragma unroll
        for (int e = 0; e < EPG; e++) acc[e] = b2s[j];
        #pragma unroll 1
        for (int k4 = 0; k4 < F / 4; k4++) {
            float wa = w2s[(4 * k4 + 0) * F + j];
            float wb = w2s[(4 * k4 + 1) * F + j];
            float wc = w2s[(4 * k4 + 2) * F + j];
            float wd = w2s[(4 * k4 + 3) * F + j];
            #pragma unroll
            for (int e = 0; e < EPG; e++) {
                float4 a = *(const float4*)&tile[(grp * EPG + e) * F + 4 * k4];
                acc[e] = fmaf(a.x, wa, fmaf(a.y, wb, fmaf(a.z, wc, fmaf(a.w, wd, acc[e]))));
            }
        }
        // epilogue: gather xh[row], modulate, scatter-add to agg[col]
        #pragma unroll
        for (int e = 0; e < EPG; e++) {
            int eg = e0 + grp * EPG + e;
            float Wv = acc[e] * g_C[eg];
            float m = g_xh[(size_t)row[eg] * F + j] * Wv;
            atomicAdd(&g_agg[(size_t)col[eg] * F + j], m);
        }
        __syncthreads();
    }
}

// ---------------- node update: h += ssp(agg@cf_w2+b2) @ lin_w + lin_b ----------------
#define SMEM_UPD ((F * H + H * H + 2 * H + TN * H) * 4)
__global__ __launch_bounds__(NT, 1) void k_update(
    const float* __restrict__ w2, const float* __restrict__ b2,
    const float* __restrict__ lw, const float* __restrict__ lb)
{
    extern __shared__ float sm[];
    float* w2s = sm;                // F*H
    float* lws = w2s + F * H;       // H*H
    float* b2s = lws + H * H;       // H
    float* lbs = b2s + H;           // H
    float* tile = lbs + H;          // TN*H (union: agg tile | s tile)
    int tid = threadIdx.x;
    int j = tid & 127;
    int grp = tid >> 7;
    for (int i = tid; i < F * H; i += NT) w2s[i] = w2[i];
    for (int i = tid; i < H * H; i += NT) lws[i] = lw[i];
    if (tid < H) { b2s[tid] = b2[tid]; lbs[tid] = lb[tid]; }
    __syncthreads();
    const int ntiles = N_NODES / TN;
    for (int t = blockIdx.x; t < ntiles; t += gridDim.x) {
        int n0 = t * TN;
        for (int i = tid; i < TN * H; i += NT) tile[i] = g_agg[(size_t)n0 * H + i];
        __syncthreads();
        float acc[EPG];
        #pragma unroll
        for (int n = 0; n < EPG; n++) acc[n] = b2s[j];
        #pragma unroll 1
        for (int k4 = 0; k4 < F / 4; k4++) {
            float wa = w2s[(4 * k4 + 0) * H + j];
            float wb = w2s[(4 * k4 + 1) * H + j];
            float wc = w2s[(4 * k4 + 2) * H + j];
            float wd = w2s[(4 * k4 + 3) * H + j];
            #pragma unroll
            for (int n = 0; n < EPG; n++) {
                float4 a = *(const float4*)&tile[(grp * EPG + n) * H + 4 * k4];
                acc[n] = fmaf(a.x, wa, fmaf(a.y, wb, fmaf(a.z, wc, fmaf(a.w, wd, acc[n]))));
            }
        }
        __syncthreads();
        #pragma unroll
        for (int n = 0; n < EPG; n++) tile[(grp * EPG + n) * H + j] = ssp(acc[n]);
        __syncthreads();
        #pragma unroll
        for (int n = 0; n < EPG; n++) acc[n] = lbs[j];
        #pragma unroll 1
        for (int k4 = 0; k4 < H / 4; k4++) {
            float wa = lws[(4 * k4 + 0) * H + j];
            float wb = lws[(4 * k4 + 1) * H + j];
            float wc = lws[(4 * k4 + 2) * H + j];
            float wd = lws[(4 * k4 + 3) * H + j];
            #pragma unroll
            for (int n = 0; n < EPG; n++) {
                float4 a = *(const float4*)&tile[(grp * EPG + n) * H + 4 * k4];
                acc[n] = fmaf(a.x, wa, fmaf(a.y, wb, fmaf(a.z, wc, fmaf(a.w, wd, acc[n]))));
            }
        }
        #pragma unroll
        for (int n = 0; n < EPG; n++) {
            int ng = n0 + grp * EPG + n;
            g_h[(size_t)ng * H + j] += acc[n];
        }
        __syncthreads();
    }
}

// ---------------- readout ----------------
#define H2 64
#define SMEM_RO ((H * H2 + H2 + H2 + TN * H + TN * 65) * 4)
__global__ __launch_bounds__(128) void k_readout(
    const float* __restrict__ w1, const float* __restrict__ b1,
    const float* __restrict__ w2, const float* __restrict__ b2,
    const int* __restrict__ batch, float* __restrict__ out)
{
    extern __shared__ float sm[];
    float* w1s = sm;                 // H*H2
    float* b1s = w1s + H * H2;       // H2
    float* w2s = b1s + H2;           // H2
    float* tile = w2s + H2;          // TN*H
    float* sbuf = tile + TN * H;     // TN*65 (padded)
    int j = threadIdx.x;
    for (int i = j; i < H * H2; i += 128) w1s[i] = w1[i];
    if (j < H2) { b1s[j] = b1[j]; w2s[j] = w2[j]; }
    float b2v = b2[0];
    __syncthreads();
    const int ntiles = N_NODES / TN;
    for (int t = blockIdx.x; t < ntiles; t += gridDim.x) {
        int n0 = t * TN;
        for (int i = j; i < TN * H; i += 128) tile[i] = g_h[(size_t)n0 * H + i];
        __syncthreads();
        if (j < H2) {
            float acc[TN];
            #pragma unroll
            for (int n = 0; n < TN; n++) acc[n] = b1s[j];
            #pragma unroll 1
            for (int k4 = 0; k4 < H / 4; k4++) {
                float wa = w1s[(4 * k4 + 0) * H2 + j];
                float wb = w1s[(4 * k4 + 1) * H2 + j];
                float wc = w1s[(4 * k4 + 2) * H2 + j];
                float wd = w1s[(4 * k4 + 3) * H2 + j];
                #pragma unroll
                for (int n = 0; n < TN; n++) {
                    float4 a = *(const float4*)&tile[n * H + 4 * k4];
                    acc[n] = fmaf(a.x, wa, fmaf(a.y, wb, fmaf(a.z, wc, fmaf(a.w, wd, acc[n]))));
                }
            }
            #pragma unroll
            for (int n = 0; n < TN; n++) sbuf[n * 65 + j] = ssp(acc[n]);
        }
        __syncthreads();
        if (j < TN) {
            int n = j;
            float v = b2v;
            #pragma unroll 1
            for (int q = 0; q < H2; q++) v += sbuf[n * 65 + q] * w2s[q];
            atomicAdd(&out[batch[n0 + n]], v);
        }
        __syncthreads();
    }
}

__global__ void k_zero_out(float* out) {
    if (threadIdx.x < NGRAPH) out[threadIdx.x] = 0.0f;
}
__global__ void k_sigmoid(float* out) {
    if (threadIdx.x < NGRAPH) {
        float v = out[threadIdx.x];
        out[threadIdx.x] = 1.0f / (1.0f + __expf(-v));
    }
}

// ---------------- host launcher ----------------
extern "C" void kernel_launch(void* const* d_in, const int* in_sizes, int n_in,
                              void* d_out, int out_size) {
    const int*   z      = (const int*)d_in[0];
    const float* pos    = (const float*)d_in[1];
    const int*   ei     = (const int*)d_in[2];
    const int*   batch  = (const int*)d_in[3];
    const float* emb    = (const float*)d_in[4];
    const float* mlp_w1 = (const float*)d_in[5];
    const float* mlp_b1 = (const float*)d_in[6];
    const float* mlp_w2 = (const float*)d_in[7];
    const float* mlp_b2 = (const float*)d_in[8];
    const float* cf_w1  = (const float*)d_in[9];
    const float* cf_w2  = (const float*)d_in[10];
    const float* cf_b2  = (const float*)d_in[11];
    const float* lin_w  = (const float*)d_in[12];
    const float* lin_b  = (const float*)d_in[13];
    const float* out_w1 = (const float*)d_in[14];
    const float* out_b1 = (const float*)d_in[15];
    const float* out_w2 = (const float*)d_in[16];
    const float* out_b2 = (const float*)d_in[17];
    float* out = (float*)d_out;

    cudaFuncSetAttribute((const void*)k_edge,    cudaFuncAttributeMaxDynamicSharedMemorySize, SMEM_EDGE);
    cudaFuncSetAttribute((const void*)k_xh,      cudaFuncAttributeMaxDynamicSharedMemorySize, SMEM_XH);
    cudaFuncSetAttribute((const void*)k_update,  cudaFuncAttributeMaxDynamicSharedMemorySize, SMEM_UPD);
    cudaFuncSetAttribute((const void*)k_readout, cudaFuncAttributeMaxDynamicSharedMemorySize, SMEM_RO);

    k_init_h<<<(N_NODES * H) / 256, 256>>>(z, emb);
    k_geom<<<N_EDGES / 128, 128>>>(pos, ei);

    for (int l = 0; l < L; l++) {
        k_xh<<<296, NT, SMEM_XH>>>(cf_w1 + (size_t)l * H * F);
        k_edge<<<296, NT, SMEM_EDGE>>>(mlp_w1 + (size_t)l * G * F,
                                       mlp_b1 + (size_t)l * F,
                                       mlp_w2 + (size_t)l * F * F,
                                       mlp_b2 + (size_t)l * F,
                                       ei);
        k_update<<<148, NT, SMEM_UPD>>>(cf_w2 + (size_t)l * F * H,
                                        cf_b2 + (size_t)l * H,
                                        lin_w + (size_t)l * H * H,
                                        lin_b + (size_t)l * H);
    }

    k_zero_out<<<1, 32>>>(out);
    k_readout<<<296, 128, SMEM_RO>>>(out_w1, out_b1, out_w2, out_b2, batch, out);
    k_sigmoid<<<1, 32>>>(out);
}